// round 15
// baseline (speedup 1.0000x reference)
#include <cuda_runtime.h>

#define NMAX 16384
#define KNN  16
#define CDIM 64
#define NODES_PER_BLOCK 4

#define GRES 16                    // grid cells per axis (coarse: R13 win)
#define GC   (GRES * GRES * GRES)  // 4096 cells -> 16KB cellStart, L1-resident
#define GB   4.5f                  // grid covers [-GB, GB]^3
#define GINVH (GRES / (2.0f * GB))
#define MARGIN 2.5f                // expected 40 in-ball pts: P(<16) ~ 1e-6
#define SURVCAP 64
#define FULLMASK 0xffffffffu
#define FINF __int_as_float(0x7f800000)

// ---- scratch (no allocation allowed) ----
__device__ float4     g_pos4[NMAX];         // orig order (fallback queries)
__device__ ulonglong2 g_pairA[NMAX / 2];    // packed candidates (fallback)
__device__ ulonglong2 g_pairB[NMAX / 2];
__device__ int    g_knn[NMAX * KNN];
__device__ int    g_flag[NMAX];
__device__ float  g_B[NMAX * CDIM];
__device__ float  g_C[NMAX * CDIM];
// grid structures
__device__ int    g_cellCnt[GC];
__device__ int    g_cellStart[GC + 1];
__device__ int    g_cellPtr[GC];
__device__ int    g_pcell[NMAX];
__device__ float4 g_spos4[NMAX];            // cell-sorted points
__device__ int    g_sid[NMAX];              // sorted -> orig index

// ---- packed f32x2 helpers ----
__device__ __forceinline__ unsigned long long pk2(float a, float b) {
    unsigned long long r;
    asm("mov.b64 %0, {%1, %2};" : "=l"(r) : "f"(a), "f"(b));
    return r;
}
__device__ __forceinline__ void upk2(unsigned long long v, float& a, float& b) {
    asm("mov.b64 {%0, %1}, %2;" : "=f"(a), "=f"(b) : "l"(v));
}
__device__ __forceinline__ unsigned long long fma2(unsigned long long a,
                                                   unsigned long long b,
                                                   unsigned long long c) {
    unsigned long long r;
    asm("fma.rn.f32x2 %0, %1, %2, %3;" : "=l"(r) : "l"(a), "l"(b), "l"(c));
    return r;
}
__device__ __forceinline__ unsigned long long mul2(unsigned long long a,
                                                   unsigned long long b) {
    unsigned long long r;
    asm("mul.rn.f32x2 %0, %1, %2;" : "=l"(r) : "l"(a), "l"(b));
    return r;
}
__device__ __forceinline__ unsigned long long add2(unsigned long long a,
                                                   unsigned long long b) {
    unsigned long long r;
    asm("add.rn.f32x2 %0, %1, %2;" : "=l"(r) : "l"(a), "l"(b));
    return r;
}
__device__ __forceinline__ unsigned long long umin64(unsigned long long a,
                                                     unsigned long long b) {
    return a < b ? a : b;
}

// predicated shared store (no BSSY/BSYNC; R7 lesson)
__device__ __forceinline__ void sts_pred(unsigned long long* p,
                                         unsigned long long v, int pred) {
    unsigned addr = (unsigned)__cvta_generic_to_shared(p);
    asm volatile(
        "{ .reg .pred q; setp.ne.s32 q, %2, 0; @q st.shared.u64 [%0], %1; }"
        :: "r"(addr), "l"(v), "r"(pred) : "memory");
}

// analytic radius^2: expected #points within r = KNN*MARGIN for pos~N(0,I3)
// UNCAPPED (R15): coverage is exact for any r because cell1d clamps --
// edge cells hold all points beyond +-GB and any ball reaching past the
// boundary includes those edge cells in its box.
__device__ __forceinline__ float knn_thr(float qw, int n) {
    const float c0 = (KNN * MARGIN * 3.0f) /
                     (4.0f * 3.14159265f * 0.06349364f * (float)n);
    float r3 = c0 * __expf(0.5f * qw);
    return __powf(r3, 0.6666667f);
}

__device__ __forceinline__ int cell1d(float v) {
    int c = (int)floorf((v + GB) * GINVH);
    return min(GRES - 1, max(0, c));
}

// ============================================================
// Kernel A: zero cell counters
// ============================================================
__global__ void zero_cells_kernel() {
    int i = blockIdx.x * blockDim.x + threadIdx.x;
    if (i < GC) g_cellCnt[i] = 0;
}

// ============================================================
// Kernel 0: pack pos (orig order + fallback pair layout) + bin count
// ============================================================
__global__ void pack_pos_kernel(const float* __restrict__ pos, int n) {
    int i = blockIdx.x * blockDim.x + threadIdx.x;
    if (i < n / 2) {
        int a = 2 * i, b = 2 * i + 1;
        float xa = pos[a * 3 + 0], ya = pos[a * 3 + 1], za = pos[a * 3 + 2];
        float xb = pos[b * 3 + 0], yb = pos[b * 3 + 1], zb = pos[b * 3 + 2];
        float wa = fmaf(xa, xa, fmaf(ya, ya, za * za));
        float wb = fmaf(xb, xb, fmaf(yb, yb, zb * zb));
        g_pos4[a] = make_float4(xa, ya, za, wa);
        g_pos4[b] = make_float4(xb, yb, zb, wb);
        g_pairA[i] = make_ulonglong2(pk2(xa, xb), pk2(ya, yb));
        g_pairB[i] = make_ulonglong2(pk2(za, zb), pk2(wa, wb));
        int ca = (cell1d(za) * GRES + cell1d(ya)) * GRES + cell1d(xa);
        int cb = (cell1d(zb) * GRES + cell1d(yb)) * GRES + cell1d(xb);
        g_pcell[a] = ca;
        g_pcell[b] = cb;
        atomicAdd(&g_cellCnt[ca], 1);
        atomicAdd(&g_cellCnt[cb], 1);
    }
}

// ============================================================
// Kernel B: exclusive prefix sum over GC cells (single block, 1024 thr)
// ============================================================
__global__ __launch_bounds__(1024)
void scan_cells_kernel() {
    __shared__ int sh[1024];
    const int t = threadIdx.x;
    const int base = t * (GC / 1024);          // 4 cells per thread
    int loc[GC / 1024];
    int s = 0;
#pragma unroll
    for (int i = 0; i < GC / 1024; i++) { loc[i] = s; s += g_cellCnt[base + i]; }
    sh[t] = s;
    __syncthreads();
    for (int d = 1; d < 1024; d <<= 1) {       // Hillis-Steele inclusive scan
        int v = (t >= d) ? sh[t - d] : 0;
        __syncthreads();
        sh[t] += v;
        __syncthreads();
    }
    int off = sh[t] - s;                       // exclusive prefix of totals
#pragma unroll
    for (int i = 0; i < GC / 1024; i++) {
        int v = off + loc[i];
        g_cellStart[base + i] = v;
        g_cellPtr[base + i]   = v;
    }
    if (t == 1023) g_cellStart[GC] = off + s;
}

// ============================================================
// Kernel C: scatter points into cell-sorted order
// ============================================================
__global__ void scatter_kernel(int n) {
    int i = blockIdx.x * blockDim.x + threadIdx.x;
    if (i < n) {
        int dst = atomicAdd(&g_cellPtr[g_pcell[i]], 1);
        g_spos4[dst] = g_pos4[i];
        g_sid[dst]   = i;
    }
}

// ============================================================
// Kernel 1a: grid KNN — WARP per sorted query, APPEND-THEN-SELECT.
// (R13 proven, with uncapped thr)
// ============================================================
__global__ __launch_bounds__(256)
void knn_grid_kernel(int n) {
    __shared__ unsigned long long surv[8][SURVCAP];

    const int w    = threadIdx.x >> 5;
    const int lane = threadIdx.x & 31;
    const int s    = blockIdx.x * 8 + w;       // sorted query index

    const float4 qp = g_spos4[s];
    const float thr = knn_thr(qp.w, n);        // UNCAPPED (R15)
    const float r   = sqrtf(thr);

    const int lx = cell1d(qp.x - r), hx = cell1d(qp.x + r);
    const int ly = cell1d(qp.y - r), hy = cell1d(qp.y + r);
    const int lz = cell1d(qp.z - r), hz = cell1d(qp.z + r);

    surv[w][lane]      = ~0ULL;
    surv[w][lane + 32] = ~0ULL;

    int cnt = 0;
    const unsigned below = (1u << lane) - 1u;

    for (int cz = lz; cz <= hz; cz++) {
        for (int cy = ly; cy <= hy; cy++) {
            const int rowb = (cz * GRES + cy) * GRES;
            const int t0 = g_cellStart[rowb + lx];     // warp-uniform, L1
            const int t1 = g_cellStart[rowb + hx + 1];
            for (int tb = t0; tb < t1; tb += 32) {
                const int t  = tb + lane;
                const int tc = min(t, n - 1);
                float4 p = g_spos4[tc];                // coalesced LDG.128
                int   oj = g_sid[tc];
                float dot = fmaf(qp.x, p.x, fmaf(qp.y, p.y, qp.z * p.z));
                float d = fmaf(-2.0f, dot, qp.w + p.w);   // ref formula
                int valid = (t < t1) & (t != s) & (d < thr);
                unsigned long long key =
                    (((unsigned long long)__float_as_uint(fmaxf(d, 0.0f))) << 32)
                    | (unsigned)oj;
                unsigned m = __ballot_sync(FULLMASK, valid != 0);
                int idx = cnt + __popc(m & below);
                sts_pred(&surv[w][min(idx, SURVCAP - 1)], key,
                         valid & (idx < SURVCAP));
                cnt += __popc(m);
            }
        }
    }
    __syncwarp();

    const int orig = g_sid[s];
    const int bad = (cnt < KNN) | (cnt > SURVCAP);
    if (lane == 0) g_flag[orig] = bad;
    if (!bad) {                                // warp-uniform
        unsigned long long a = surv[w][lane];
        unsigned long long b = surv[w][lane + 32];
        unsigned long long keep = ~0ULL;
#pragma unroll
        for (int rr = 0; rr < KNN; rr++) {
            unsigned long long mn = umin64(a, b);
#pragma unroll
            for (int off = 16; off; off >>= 1)
                mn = umin64(mn, __shfl_xor_sync(FULLMASK, mn, off));
            if (lane == rr) keep = mn;         // SEL, no branch
            if (a == mn) a = ~0ULL;            // keys unique (idx unique)
            if (b == mn) b = ~0ULL;
        }
        if (lane < KNN)
            g_knn[orig * KNN + lane] = (int)(keep & 0xffffffffu);
    }
}

// ============================================================
// Kernel 1b: exact fallback for flagged queries (R13, now ~0 flagged)
// ============================================================
__device__ __forceinline__ void warp_insert64(unsigned long long kn,
                                              unsigned long long& bk,
                                              unsigned long long& worst,
                                              int lane) {
    unsigned long long bp = __shfl_up_sync(FULLMASK, bk, 1);
    unsigned gm = __ballot_sync(FULLMASK, (lane < KNN) && (bk > kn));
    int pos = __ffs(gm) - 1;            // gm != 0 since bk[15] > kn
    if (lane < KNN) {
        if (lane > pos)       bk = bp;
        else if (lane == pos) bk = kn;
    }
    worst = __shfl_sync(FULLMASK, bk, KNN - 1);
}

__global__ __launch_bounds__(256)
void knn_fallback_kernel(int n) {
    const int lane = threadIdx.x & 31;
    const int q    = blockIdx.x * 8 + (threadIdx.x >> 5);
    if (g_flag[q] == 0) return;       // warp-uniform

    const float4 qp = g_pos4[q];
    const unsigned long long qx2 = pk2(qp.x, qp.x);
    const unsigned long long qy2 = pk2(qp.y, qp.y);
    const unsigned long long qz2 = pk2(qp.z, qp.z);
    const unsigned long long qw2 = pk2(qp.w, qp.w);
    const unsigned long long M2  = pk2(-2.0f, -2.0f);

    unsigned long long bk = ~0ULL;
    unsigned long long worst = ~0ULL;

    for (int base = 0; base < n / 2; base += 32) {
        ulonglong2 A = g_pairA[base + lane];
        ulonglong2 B = g_pairB[base + lane];
        unsigned long long acc = mul2(qz2, B.x);
        acc = fma2(qy2, A.y, acc);
        acc = fma2(qx2, A.x, acc);
        unsigned long long dd = fma2(M2, acc, add2(qw2, B.y));
        float d0, d1;
        upk2(dd, d0, d1);
        int j0 = 2 * (base + lane);
        unsigned long long k0 =
            (((unsigned long long)__float_as_uint(fmaxf(d0, 0.0f))) << 32)
            | (unsigned)j0;
        unsigned long long k1 =
            (((unsigned long long)__float_as_uint(fmaxf(d1, 0.0f))) << 32)
            | (unsigned)(j0 + 1);
        bool v0 = (k0 < worst) && (j0 != q);
        bool v1 = (k1 < worst) && (j0 + 1 != q);

        unsigned m = __ballot_sync(FULLMASK, v0 | v1);
        while (m) {
            int src = __ffs(m) - 1;
            m &= m - 1;
            unsigned long long e0 = __shfl_sync(FULLMASK, k0, src);
            unsigned long long e1 = __shfl_sync(FULLMASK, k1, src);
            int jj = __shfl_sync(FULLMASK, j0, src);
            if (e0 < worst && jj != q)
                warp_insert64(e0, bk, worst, lane);
            if (e1 < worst && jj + 1 != q)
                warp_insert64(e1, bk, worst, lane);
        }
    }

    if (lane < KNN)
        g_knn[q * KNN + lane] = (int)(bk & 0xffffffffu);
}

// ============================================================
// Kernel 2: B = x @ W1b ; C = x @ (W1a - W1b) + b1  (4-node blocked)
// ============================================================
__global__ __launch_bounds__(256)
void feat_kernel(const float* __restrict__ x,
                 const float* __restrict__ W1,
                 const float* __restrict__ b1, int n) {
    int t   = blockIdx.x * blockDim.x + threadIdx.x;
    int grp = t >> 6;
    int d   = t & 63;
    int n0  = grp * 4;
    if (n0 >= n) return;

    const float* x0 = x + n0 * CDIM;
    float a0 = 0, a1 = 0, a2 = 0, a3 = 0;
    float b0 = 0, b1v = 0, b2v = 0, b3 = 0;
#pragma unroll 8
    for (int c = 0; c < CDIM; c++) {
        float wa = W1[c * CDIM + d];
        float wb = W1[(CDIM + c) * CDIM + d];
        float x0v = x0[c];
        float x1v = x0[CDIM + c];
        float x2v = x0[2 * CDIM + c];
        float x3v = x0[3 * CDIM + c];
        a0 = fmaf(x0v, wa, a0);  b0  = fmaf(x0v, wb, b0);
        a1 = fmaf(x1v, wa, a1);  b1v = fmaf(x1v, wb, b1v);
        a2 = fmaf(x2v, wa, a2);  b2v = fmaf(x2v, wb, b2v);
        a3 = fmaf(x3v, wa, a3);  b3  = fmaf(x3v, wb, b3);
    }
    float bias = b1[d];
    g_B[(n0 + 0) * CDIM + d] = b0;   g_C[(n0 + 0) * CDIM + d] = a0 - b0  + bias;
    g_B[(n0 + 1) * CDIM + d] = b1v;  g_C[(n0 + 1) * CDIM + d] = a1 - b1v + bias;
    g_B[(n0 + 2) * CDIM + d] = b2v;  g_C[(n0 + 2) * CDIM + d] = a2 - b2v + bias;
    g_B[(n0 + 3) * CDIM + d] = b3;   g_C[(n0 + 3) * CDIM + d] = a3 - b3  + bias;
}

// ============================================================
// Kernel 3: edge — PROVEN R8/R13 monolithic e-outer kernel (88us).
// ============================================================
#define GSTRIDE 20
__global__ __launch_bounds__(64)
void edge_kernel(const float* __restrict__ W2,
                 const float* __restrict__ b2,
                 float* __restrict__ out, int n) {
    __shared__ __align__(16) float gsT[2][CDIM][GSTRIDE];
    const int d = threadIdx.x;
    const float b2d = b2[d];
    const int n0 = blockIdx.x * NODES_PER_BLOCK;

    float bv[KNN];
    float cv;
    {
        const int4* jr = (const int4*)&g_knn[n0 * KNN];
        int4 j4[4];
#pragma unroll
        for (int v = 0; v < 4; v++) j4[v] = jr[v];
        const int* jv = (const int*)j4;
        cv = g_C[n0 * CDIM + d];
#pragma unroll
        for (int k = 0; k < KNN; k++)
            bv[k] = g_B[jv[k] * CDIM + d];
    }

    for (int i = 0; i < NODES_PER_BLOCK; i++) {
        const int buf = i & 1;
        const int nn  = n0 + i;

#pragma unroll
        for (int k2 = 0; k2 < KNN / 2; k2++) {
            float2 gg;
            gg.x = fmaxf(cv + bv[2 * k2],     0.0f);
            gg.y = fmaxf(cv + bv[2 * k2 + 1], 0.0f);
            *(float2*)&gsT[buf][d][2 * k2] = gg;
        }

        if (i + 1 < NODES_PER_BLOCK) {
            const int nn1 = nn + 1;
            const int4* jr = (const int4*)&g_knn[nn1 * KNN];
            int4 j4[4];
#pragma unroll
            for (int v = 0; v < 4; v++) j4[v] = jr[v];
            const int* jv = (const int*)j4;
            cv = g_C[nn1 * CDIM + d];
#pragma unroll
            for (int k = 0; k < KNN; k++)
                bv[k] = g_B[jv[k] * CDIM + d];
        }
        __syncthreads();

        unsigned long long acc[8];
#pragma unroll
        for (int j = 0; j < 8; j++) acc[j] = 0ULL;
#pragma unroll 8
        for (int e = 0; e < CDIM; e++) {
            float wv = W2[e * CDIM + d];
            unsigned long long w2 = pk2(wv, wv);
            const ulonglong2* gp = (const ulonglong2*)&gsT[buf][e][0];
            ulonglong2 Ga = gp[0];
            ulonglong2 Gb = gp[1];
            acc[0] = fma2(Ga.x, w2, acc[0]);
            acc[1] = fma2(Ga.y, w2, acc[1]);
            acc[2] = fma2(Gb.x, w2, acc[2]);
            acc[3] = fma2(Gb.y, w2, acc[3]);
            const ulonglong2* gq = (const ulonglong2*)&gsT[buf][e][8];
            ulonglong2 Gc = gq[0];
            ulonglong2 Gd = gq[1];
            acc[4] = fma2(Gc.x, w2, acc[4]);
            acc[5] = fma2(Gd.x, w2, acc[5]);
            acc[6] = fma2(Gc.y, w2, acc[6]);
            acc[7] = fma2(Gd.y, w2, acc[7]);
        }
        float m = -3.4e38f;
#pragma unroll
        for (int j = 0; j < 8; j++) {
            float lo, hi;
            upk2(acc[j], lo, hi);
            m = fmaxf(m, fmaxf(lo, hi));
        }
        out[nn * CDIM + d] = m + b2d;
    }
}

// ============================================================
extern "C" void kernel_launch(void* const* d_in, const int* in_sizes, int n_in,
                              void* d_out, int out_size) {
    const float* x   = (const float*)d_in[0];
    const float* pos = (const float*)d_in[1];
    const float* W1  = (const float*)d_in[2];
    const float* b1  = (const float*)d_in[3];
    const float* W2  = (const float*)d_in[4];
    const float* b2  = (const float*)d_in[5];
    float* out = (float*)d_out;

    int n = in_sizes[1] / 3;
    if (n > NMAX) n = NMAX;

    zero_cells_kernel<<<GC / 256, 256>>>();
    pack_pos_kernel<<<(n / 2 + 255) / 256, 256>>>(pos, n);
    scan_cells_kernel<<<1, 1024>>>();
    scatter_kernel<<<(n + 255) / 256, 256>>>(n);
    knn_grid_kernel<<<(n + 7) / 8, 256>>>(n);
    knn_fallback_kernel<<<n / 8, 256>>>(n);
    feat_kernel<<<(n * CDIM / 4 + 255) / 256, 256>>>(x, W1, b1, n);
    edge_kernel<<<n / NODES_PER_BLOCK, CDIM>>>(W2, b2, out, n);
}

// round 16
// speedup vs baseline: 1.7360x; 1.7360x over previous
#include <cuda_runtime.h>

#define NMAX 16384
#define KNN  16
#define CDIM 64
#define NODES_PER_BLOCK 4

#define GRES 16                    // grid cells per axis (coarse: R13 win)
#define GC   (GRES * GRES * GRES)  // 4096 cells -> 16KB cellStart, L1-resident
#define GB   4.5f                  // grid covers [-GB, GB]^3
#define GINVH (GRES / (2.0f * GB))
#define MARGIN 2.0f                // R13 proven
#define RCAP2 2.25f                // r^2 cap (outliers -> flagged -> fallback)
#define SURVCAP 64
#define FULLMASK 0xffffffffu
#define FINF __int_as_float(0x7f800000)

// ---- scratch (no allocation allowed) ----
__device__ float4     g_pos4[NMAX];         // orig order (fallback queries)
__device__ ulonglong2 g_pairA[NMAX / 2];    // packed candidates (fallback)
__device__ ulonglong2 g_pairB[NMAX / 2];
__device__ int    g_knn[NMAX * KNN];
__device__ int    g_flag[NMAX];
__device__ float  g_B[NMAX * CDIM];
__device__ float  g_C[NMAX * CDIM];
// grid structures
__device__ int    g_cellCnt[GC];
__device__ int    g_cellStart[GC + 1];
__device__ int    g_cellPtr[GC];
__device__ int    g_pcell[NMAX];
__device__ float4 g_spos4[NMAX];            // cell-sorted points
__device__ int    g_sid[NMAX];              // sorted -> orig index

// ---- packed f32x2 helpers ----
__device__ __forceinline__ unsigned long long pk2(float a, float b) {
    unsigned long long r;
    asm("mov.b64 %0, {%1, %2};" : "=l"(r) : "f"(a), "f"(b));
    return r;
}
__device__ __forceinline__ void upk2(unsigned long long v, float& a, float& b) {
    asm("mov.b64 {%0, %1}, %2;" : "=f"(a), "=f"(b) : "l"(v));
}
__device__ __forceinline__ unsigned long long fma2(unsigned long long a,
                                                   unsigned long long b,
                                                   unsigned long long c) {
    unsigned long long r;
    asm("fma.rn.f32x2 %0, %1, %2, %3;" : "=l"(r) : "l"(a), "l"(b), "l"(c));
    return r;
}
__device__ __forceinline__ unsigned long long mul2(unsigned long long a,
                                                   unsigned long long b) {
    unsigned long long r;
    asm("mul.rn.f32x2 %0, %1, %2;" : "=l"(r) : "l"(a), "l"(b));
    return r;
}
__device__ __forceinline__ unsigned long long add2(unsigned long long a,
                                                   unsigned long long b) {
    unsigned long long r;
    asm("add.rn.f32x2 %0, %1, %2;" : "=l"(r) : "l"(a), "l"(b));
    return r;
}
__device__ __forceinline__ unsigned long long umin64(unsigned long long a,
                                                     unsigned long long b) {
    return a < b ? a : b;
}

// predicated shared store (no BSSY/BSYNC; R7 lesson)
__device__ __forceinline__ void sts_pred(unsigned long long* p,
                                         unsigned long long v, int pred) {
    unsigned addr = (unsigned)__cvta_generic_to_shared(p);
    asm volatile(
        "{ .reg .pred q; setp.ne.s32 q, %2, 0; @q st.shared.u64 [%0], %1; }"
        :: "r"(addr), "l"(v), "r"(pred) : "memory");
}

// analytic radius^2: expected #points within r = KNN*MARGIN for pos~N(0,I3)
__device__ __forceinline__ float knn_thr(float qw, int n) {
    const float c0 = (KNN * MARGIN * 3.0f) /
                     (4.0f * 3.14159265f * 0.06349364f * (float)n);
    float r3 = c0 * __expf(0.5f * qw);
    return __powf(r3, 0.6666667f);
}

__device__ __forceinline__ int cell1d(float v) {
    int c = (int)floorf((v + GB) * GINVH);
    return min(GRES - 1, max(0, c));
}

// ============================================================
// Kernel A: zero cell counters
// ============================================================
__global__ void zero_cells_kernel() {
    int i = blockIdx.x * blockDim.x + threadIdx.x;
    if (i < GC) g_cellCnt[i] = 0;
}

// ============================================================
// Kernel 0: pack pos (orig order + fallback pair layout) + bin count
// ============================================================
__global__ void pack_pos_kernel(const float* __restrict__ pos, int n) {
    int i = blockIdx.x * blockDim.x + threadIdx.x;
    if (i < n / 2) {
        int a = 2 * i, b = 2 * i + 1;
        float xa = pos[a * 3 + 0], ya = pos[a * 3 + 1], za = pos[a * 3 + 2];
        float xb = pos[b * 3 + 0], yb = pos[b * 3 + 1], zb = pos[b * 3 + 2];
        float wa = fmaf(xa, xa, fmaf(ya, ya, za * za));
        float wb = fmaf(xb, xb, fmaf(yb, yb, zb * zb));
        g_pos4[a] = make_float4(xa, ya, za, wa);
        g_pos4[b] = make_float4(xb, yb, zb, wb);
        g_pairA[i] = make_ulonglong2(pk2(xa, xb), pk2(ya, yb));
        g_pairB[i] = make_ulonglong2(pk2(za, zb), pk2(wa, wb));
        int ca = (cell1d(za) * GRES + cell1d(ya)) * GRES + cell1d(xa);
        int cb = (cell1d(zb) * GRES + cell1d(yb)) * GRES + cell1d(xb);
        g_pcell[a] = ca;
        g_pcell[b] = cb;
        atomicAdd(&g_cellCnt[ca], 1);
        atomicAdd(&g_cellCnt[cb], 1);
    }
}

// ============================================================
// Kernel B: exclusive prefix sum over GC cells (single block, 1024 thr)
// ============================================================
__global__ __launch_bounds__(1024)
void scan_cells_kernel() {
    __shared__ int sh[1024];
    const int t = threadIdx.x;
    const int base = t * (GC / 1024);          // 4 cells per thread
    int loc[GC / 1024];
    int s = 0;
#pragma unroll
    for (int i = 0; i < GC / 1024; i++) { loc[i] = s; s += g_cellCnt[base + i]; }
    sh[t] = s;
    __syncthreads();
    for (int d = 1; d < 1024; d <<= 1) {       // Hillis-Steele inclusive scan
        int v = (t >= d) ? sh[t - d] : 0;
        __syncthreads();
        sh[t] += v;
        __syncthreads();
    }
    int off = sh[t] - s;                       // exclusive prefix of totals
#pragma unroll
    for (int i = 0; i < GC / 1024; i++) {
        int v = off + loc[i];
        g_cellStart[base + i] = v;
        g_cellPtr[base + i]   = v;
    }
    if (t == 1023) g_cellStart[GC] = off + s;
}

// ============================================================
// Kernel C: scatter points into cell-sorted order
// ============================================================
__global__ void scatter_kernel(int n) {
    int i = blockIdx.x * blockDim.x + threadIdx.x;
    if (i < n) {
        int dst = atomicAdd(&g_cellPtr[g_pcell[i]], 1);
        g_spos4[dst] = g_pos4[i];
        g_sid[dst]   = i;
    }
}

// ============================================================
// Kernel 1a: grid KNN — WARP per sorted query, APPEND-THEN-SELECT
// (R13 proven scan semantics), with one change: ROW-BOUNDS PREFETCH.
// Lane i loads row i's [t0,t1) in parallel (MLP overlaps the L1/L2
// latency of the serially-dependent per-row cellStart loads R13 paid),
// then the row loop gets bounds via shfl — no memory on critical path.
// Scanned set / keys / certificate identical to R13.
// ============================================================
__global__ __launch_bounds__(256)
void knn_grid_kernel(int n) {
    __shared__ unsigned long long surv[8][SURVCAP];

    const int w    = threadIdx.x >> 5;
    const int lane = threadIdx.x & 31;
    const int s    = blockIdx.x * 8 + w;       // sorted query index

    const float4 qp = g_spos4[s];
    const float thr = fminf(knn_thr(qp.w, n), RCAP2);
    const float r   = sqrtf(thr);

    const int lx = cell1d(qp.x - r), hx = cell1d(qp.x + r);
    const int ly = cell1d(qp.y - r), hy = cell1d(qp.y + r);
    const int lz = cell1d(qp.z - r), hz = cell1d(qp.z + r);
    const int ny = hy - ly + 1;
    const int nrows = ny * (hz - lz + 1);      // <= 49 when cap-hit

    surv[w][lane]      = ~0ULL;
    surv[w][lane + 32] = ~0ULL;

    int cnt = 0;
    const unsigned below = (1u << lane) - 1u;

    for (int rb = 0; rb < nrows; rb += 32) {
        // parallel row-bounds prefetch: lane i -> row rb+i
        int ri = rb + lane;
        int s0 = 0, e0 = 0;
        if (ri < nrows) {
            int cz = lz + ri / ny;
            int cy = ly + ri - (ri / ny) * ny;
            int rowb = (cz * GRES + cy) * GRES;
            s0 = g_cellStart[rowb + lx];
            e0 = g_cellStart[rowb + hx + 1];
        }
        const int rcnt = min(32, nrows - rb);
        for (int rr = 0; rr < rcnt; rr++) {    // warp-uniform
            const int t0 = __shfl_sync(FULLMASK, s0, rr);
            const int t1 = __shfl_sync(FULLMASK, e0, rr);
            for (int tb = t0; tb < t1; tb += 32) {
                const int t  = tb + lane;
                const int tc = min(t, n - 1);
                float4 p = g_spos4[tc];                // coalesced LDG.128
                int   oj = g_sid[tc];
                float dot = fmaf(qp.x, p.x, fmaf(qp.y, p.y, qp.z * p.z));
                float d = fmaf(-2.0f, dot, qp.w + p.w);   // ref formula
                int valid = (t < t1) & (t != s) & (d < thr);
                unsigned long long key =
                    (((unsigned long long)__float_as_uint(fmaxf(d, 0.0f))) << 32)
                    | (unsigned)oj;
                unsigned m = __ballot_sync(FULLMASK, valid != 0);
                int idx = cnt + __popc(m & below);
                sts_pred(&surv[w][min(idx, SURVCAP - 1)], key,
                         valid & (idx < SURVCAP));
                cnt += __popc(m);
            }
        }
    }
    __syncwarp();

    const int orig = g_sid[s];
    const int bad = (cnt < KNN) | (cnt > SURVCAP);
    if (lane == 0) g_flag[orig] = bad;
    if (!bad) {                                // warp-uniform
        unsigned long long a = surv[w][lane];
        unsigned long long b = surv[w][lane + 32];
        unsigned long long keep = ~0ULL;
#pragma unroll
        for (int rr = 0; rr < KNN; rr++) {
            unsigned long long mn = umin64(a, b);
#pragma unroll
            for (int off = 16; off; off >>= 1)
                mn = umin64(mn, __shfl_xor_sync(FULLMASK, mn, off));
            if (lane == rr) keep = mn;         // SEL, no branch
            if (a == mn) a = ~0ULL;            // keys unique (idx unique)
            if (b == mn) b = ~0ULL;
        }
        if (lane < KNN)
            g_knn[orig * KNN + lane] = (int)(keep & 0xffffffffu);
    }
}

// ============================================================
// Kernel 1b: exact fallback for flagged queries (identical to R13)
// ============================================================
__device__ __forceinline__ void warp_insert64(unsigned long long kn,
                                              unsigned long long& bk,
                                              unsigned long long& worst,
                                              int lane) {
    unsigned long long bp = __shfl_up_sync(FULLMASK, bk, 1);
    unsigned gm = __ballot_sync(FULLMASK, (lane < KNN) && (bk > kn));
    int pos = __ffs(gm) - 1;            // gm != 0 since bk[15] > kn
    if (lane < KNN) {
        if (lane > pos)       bk = bp;
        else if (lane == pos) bk = kn;
    }
    worst = __shfl_sync(FULLMASK, bk, KNN - 1);
}

__global__ __launch_bounds__(256)
void knn_fallback_kernel(int n) {
    const int lane = threadIdx.x & 31;
    const int q    = blockIdx.x * 8 + (threadIdx.x >> 5);
    if (g_flag[q] == 0) return;       // warp-uniform

    const float4 qp = g_pos4[q];
    const unsigned long long qx2 = pk2(qp.x, qp.x);
    const unsigned long long qy2 = pk2(qp.y, qp.y);
    const unsigned long long qz2 = pk2(qp.z, qp.z);
    const unsigned long long qw2 = pk2(qp.w, qp.w);
    const unsigned long long M2  = pk2(-2.0f, -2.0f);

    unsigned long long bk = ~0ULL;
    unsigned long long worst = ~0ULL;

    for (int base = 0; base < n / 2; base += 32) {
        ulonglong2 A = g_pairA[base + lane];
        ulonglong2 B = g_pairB[base + lane];
        unsigned long long acc = mul2(qz2, B.x);
        acc = fma2(qy2, A.y, acc);
        acc = fma2(qx2, A.x, acc);
        unsigned long long dd = fma2(M2, acc, add2(qw2, B.y));
        float d0, d1;
        upk2(dd, d0, d1);
        int j0 = 2 * (base + lane);
        unsigned long long k0 =
            (((unsigned long long)__float_as_uint(fmaxf(d0, 0.0f))) << 32)
            | (unsigned)j0;
        unsigned long long k1 =
            (((unsigned long long)__float_as_uint(fmaxf(d1, 0.0f))) << 32)
            | (unsigned)(j0 + 1);
        bool v0 = (k0 < worst) && (j0 != q);
        bool v1 = (k1 < worst) && (j0 + 1 != q);

        unsigned m = __ballot_sync(FULLMASK, v0 | v1);
        while (m) {
            int src = __ffs(m) - 1;
            m &= m - 1;
            unsigned long long e0 = __shfl_sync(FULLMASK, k0, src);
            unsigned long long e1 = __shfl_sync(FULLMASK, k1, src);
            int jj = __shfl_sync(FULLMASK, j0, src);
            if (e0 < worst && jj != q)
                warp_insert64(e0, bk, worst, lane);
            if (e1 < worst && jj + 1 != q)
                warp_insert64(e1, bk, worst, lane);
        }
    }

    if (lane < KNN)
        g_knn[q * KNN + lane] = (int)(bk & 0xffffffffu);
}

// ============================================================
// Kernel 2: B = x @ W1b ; C = x @ (W1a - W1b) + b1  (4-node blocked)
// ============================================================
__global__ __launch_bounds__(256)
void feat_kernel(const float* __restrict__ x,
                 const float* __restrict__ W1,
                 const float* __restrict__ b1, int n) {
    int t   = blockIdx.x * blockDim.x + threadIdx.x;
    int grp = t >> 6;
    int d   = t & 63;
    int n0  = grp * 4;
    if (n0 >= n) return;

    const float* x0 = x + n0 * CDIM;
    float a0 = 0, a1 = 0, a2 = 0, a3 = 0;
    float b0 = 0, b1v = 0, b2v = 0, b3 = 0;
#pragma unroll 8
    for (int c = 0; c < CDIM; c++) {
        float wa = W1[c * CDIM + d];
        float wb = W1[(CDIM + c) * CDIM + d];
        float x0v = x0[c];
        float x1v = x0[CDIM + c];
        float x2v = x0[2 * CDIM + c];
        float x3v = x0[3 * CDIM + c];
        a0 = fmaf(x0v, wa, a0);  b0  = fmaf(x0v, wb, b0);
        a1 = fmaf(x1v, wa, a1);  b1v = fmaf(x1v, wb, b1v);
        a2 = fmaf(x2v, wa, a2);  b2v = fmaf(x2v, wb, b2v);
        a3 = fmaf(x3v, wa, a3);  b3  = fmaf(x3v, wb, b3);
    }
    float bias = b1[d];
    g_B[(n0 + 0) * CDIM + d] = b0;   g_C[(n0 + 0) * CDIM + d] = a0 - b0  + bias;
    g_B[(n0 + 1) * CDIM + d] = b1v;  g_C[(n0 + 1) * CDIM + d] = a1 - b1v + bias;
    g_B[(n0 + 2) * CDIM + d] = b2v;  g_C[(n0 + 2) * CDIM + d] = a2 - b2v + bias;
    g_B[(n0 + 3) * CDIM + d] = b3;   g_C[(n0 + 3) * CDIM + d] = a3 - b3  + bias;
}

// ============================================================
// Kernel 3: edge — PROVEN R8/R13 monolithic e-outer kernel (88us).
// ============================================================
#define GSTRIDE 20
__global__ __launch_bounds__(64)
void edge_kernel(const float* __restrict__ W2,
                 const float* __restrict__ b2,
                 float* __restrict__ out, int n) {
    __shared__ __align__(16) float gsT[2][CDIM][GSTRIDE];
    const int d = threadIdx.x;
    const float b2d = b2[d];
    const int n0 = blockIdx.x * NODES_PER_BLOCK;

    float bv[KNN];
    float cv;
    {
        const int4* jr = (const int4*)&g_knn[n0 * KNN];
        int4 j4[4];
#pragma unroll
        for (int v = 0; v < 4; v++) j4[v] = jr[v];
        const int* jv = (const int*)j4;
        cv = g_C[n0 * CDIM + d];
#pragma unroll
        for (int k = 0; k < KNN; k++)
            bv[k] = g_B[jv[k] * CDIM + d];
    }

    for (int i = 0; i < NODES_PER_BLOCK; i++) {
        const int buf = i & 1;
        const int nn  = n0 + i;

#pragma unroll
        for (int k2 = 0; k2 < KNN / 2; k2++) {
            float2 gg;
            gg.x = fmaxf(cv + bv[2 * k2],     0.0f);
            gg.y = fmaxf(cv + bv[2 * k2 + 1], 0.0f);
            *(float2*)&gsT[buf][d][2 * k2] = gg;
        }

        if (i + 1 < NODES_PER_BLOCK) {
            const int nn1 = nn + 1;
            const int4* jr = (const int4*)&g_knn[nn1 * KNN];
            int4 j4[4];
#pragma unroll
            for (int v = 0; v < 4; v++) j4[v] = jr[v];
            const int* jv = (const int*)j4;
            cv = g_C[nn1 * CDIM + d];
#pragma unroll
            for (int k = 0; k < KNN; k++)
                bv[k] = g_B[jv[k] * CDIM + d];
        }
        __syncthreads();

        unsigned long long acc[8];
#pragma unroll
        for (int j = 0; j < 8; j++) acc[j] = 0ULL;
#pragma unroll 8
        for (int e = 0; e < CDIM; e++) {
            float wv = W2[e * CDIM + d];
            unsigned long long w2 = pk2(wv, wv);
            const ulonglong2* gp = (const ulonglong2*)&gsT[buf][e][0];
            ulonglong2 Ga = gp[0];
            ulonglong2 Gb = gp[1];
            acc[0] = fma2(Ga.x, w2, acc[0]);
            acc[1] = fma2(Ga.y, w2, acc[1]);
            acc[2] = fma2(Gb.x, w2, acc[2]);
            acc[3] = fma2(Gb.y, w2, acc[3]);
            const ulonglong2* gq = (const ulonglong2*)&gsT[buf][e][8];
            ulonglong2 Gc = gq[0];
            ulonglong2 Gd = gq[1];
            acc[4] = fma2(Gc.x, w2, acc[4]);
            acc[5] = fma2(Gd.x, w2, acc[5]);
            acc[6] = fma2(Gc.y, w2, acc[6]);
            acc[7] = fma2(Gd.y, w2, acc[7]);
        }
        float m = -3.4e38f;
#pragma unroll
        for (int j = 0; j < 8; j++) {
            float lo, hi;
            upk2(acc[j], lo, hi);
            m = fmaxf(m, fmaxf(lo, hi));
        }
        out[nn * CDIM + d] = m + b2d;
    }
}

// ============================================================
extern "C" void kernel_launch(void* const* d_in, const int* in_sizes, int n_in,
                              void* d_out, int out_size) {
    const float* x   = (const float*)d_in[0];
    const float* pos = (const float*)d_in[1];
    const float* W1  = (const float*)d_in[2];
    const float* b1  = (const float*)d_in[3];
    const float* W2  = (const float*)d_in[4];
    const float* b2  = (const float*)d_in[5];
    float* out = (float*)d_out;

    int n = in_sizes[1] / 3;
    if (n > NMAX) n = NMAX;

    zero_cells_kernel<<<GC / 256, 256>>>();
    pack_pos_kernel<<<(n / 2 + 255) / 256, 256>>>(pos, n);
    scan_cells_kernel<<<1, 1024>>>();
    scatter_kernel<<<(n + 255) / 256, 256>>>(n);
    knn_grid_kernel<<<(n + 7) / 8, 256>>>(n);
    knn_fallback_kernel<<<n / 8, 256>>>(n);
    feat_kernel<<<(n * CDIM / 4 + 255) / 256, 256>>>(x, W1, b1, n);
    edge_kernel<<<n / NODES_PER_BLOCK, CDIM>>>(W2, b2, out, n);
}

// round 17
// speedup vs baseline: 2.1798x; 1.2557x over previous
#include <cuda_runtime.h>

#define NMAX 16384
#define KNN  16
#define CDIM 64
#define NODES_PER_BLOCK 4

#define GRES 16                    // grid cells per axis (coarse: R13 win)
#define GC   (GRES * GRES * GRES)  // 4096 cells -> 16KB cellStart, L1-resident
#define GB   4.5f                  // grid covers [-GB, GB]^3
#define GINVH (GRES / (2.0f * GB))
#define MARGIN 2.0f                // R13 proven
#define RCAP2 2.25f                // r^2 cap (outliers -> flagged -> fallback)
#define SURVCAP 64
#define FULLMASK 0xffffffffu
#define FINF __int_as_float(0x7f800000)

// ---- scratch (no allocation allowed) ----
__device__ float4     g_pos4[NMAX];         // orig order (fallback queries)
__device__ ulonglong2 g_pairA[NMAX / 2];    // packed candidates (fallback)
__device__ ulonglong2 g_pairB[NMAX / 2];
__device__ int    g_knn[NMAX * KNN];
__device__ int    g_flag[NMAX];
__device__ float  g_B[NMAX * CDIM];
__device__ float  g_C[NMAX * CDIM];
// grid structures
__device__ int    g_cellCnt[GC];
__device__ int    g_cellStart[GC + 1];
__device__ int    g_cellPtr[GC];
__device__ int    g_pcell[NMAX];
__device__ float4 g_spos4[NMAX];            // cell-sorted points
__device__ int    g_sid[NMAX];              // sorted -> orig index

// ---- packed f32x2 helpers ----
__device__ __forceinline__ unsigned long long pk2(float a, float b) {
    unsigned long long r;
    asm("mov.b64 %0, {%1, %2};" : "=l"(r) : "f"(a), "f"(b));
    return r;
}
__device__ __forceinline__ void upk2(unsigned long long v, float& a, float& b) {
    asm("mov.b64 {%0, %1}, %2;" : "=f"(a), "=f"(b) : "l"(v));
}
__device__ __forceinline__ unsigned long long fma2(unsigned long long a,
                                                   unsigned long long b,
                                                   unsigned long long c) {
    unsigned long long r;
    asm("fma.rn.f32x2 %0, %1, %2, %3;" : "=l"(r) : "l"(a), "l"(b), "l"(c));
    return r;
}
__device__ __forceinline__ unsigned long long mul2(unsigned long long a,
                                                   unsigned long long b) {
    unsigned long long r;
    asm("mul.rn.f32x2 %0, %1, %2;" : "=l"(r) : "l"(a), "l"(b));
    return r;
}
__device__ __forceinline__ unsigned long long add2(unsigned long long a,
                                                   unsigned long long b) {
    unsigned long long r;
    asm("add.rn.f32x2 %0, %1, %2;" : "=l"(r) : "l"(a), "l"(b));
    return r;
}
__device__ __forceinline__ unsigned long long umin64(unsigned long long a,
                                                     unsigned long long b) {
    return a < b ? a : b;
}

// predicated shared store (no BSSY/BSYNC; R7 lesson)
__device__ __forceinline__ void sts_pred(unsigned long long* p,
                                         unsigned long long v, int pred) {
    unsigned addr = (unsigned)__cvta_generic_to_shared(p);
    asm volatile(
        "{ .reg .pred q; setp.ne.s32 q, %2, 0; @q st.shared.u64 [%0], %1; }"
        :: "r"(addr), "l"(v), "r"(pred) : "memory");
}

// analytic radius^2: expected #points within r = KNN*MARGIN for pos~N(0,I3)
__device__ __forceinline__ float knn_thr(float qw, int n) {
    const float c0 = (KNN * MARGIN * 3.0f) /
                     (4.0f * 3.14159265f * 0.06349364f * (float)n);
    float r3 = c0 * __expf(0.5f * qw);
    return __powf(r3, 0.6666667f);
}

__device__ __forceinline__ int cell1d(float v) {
    int c = (int)floorf((v + GB) * GINVH);
    return min(GRES - 1, max(0, c));
}

// ============================================================
// Kernel A: zero cell counters
// ============================================================
__global__ void zero_cells_kernel() {
    int i = blockIdx.x * blockDim.x + threadIdx.x;
    if (i < GC) g_cellCnt[i] = 0;
}

// ============================================================
// Kernel 0: pack pos (orig order + fallback pair layout) + bin count
// ============================================================
__global__ void pack_pos_kernel(const float* __restrict__ pos, int n) {
    int i = blockIdx.x * blockDim.x + threadIdx.x;
    if (i < n / 2) {
        int a = 2 * i, b = 2 * i + 1;
        float xa = pos[a * 3 + 0], ya = pos[a * 3 + 1], za = pos[a * 3 + 2];
        float xb = pos[b * 3 + 0], yb = pos[b * 3 + 1], zb = pos[b * 3 + 2];
        float wa = fmaf(xa, xa, fmaf(ya, ya, za * za));
        float wb = fmaf(xb, xb, fmaf(yb, yb, zb * zb));
        g_pos4[a] = make_float4(xa, ya, za, wa);
        g_pos4[b] = make_float4(xb, yb, zb, wb);
        g_pairA[i] = make_ulonglong2(pk2(xa, xb), pk2(ya, yb));
        g_pairB[i] = make_ulonglong2(pk2(za, zb), pk2(wa, wb));
        int ca = (cell1d(za) * GRES + cell1d(ya)) * GRES + cell1d(xa);
        int cb = (cell1d(zb) * GRES + cell1d(yb)) * GRES + cell1d(xb);
        g_pcell[a] = ca;
        g_pcell[b] = cb;
        atomicAdd(&g_cellCnt[ca], 1);
        atomicAdd(&g_cellCnt[cb], 1);
    }
}

// ============================================================
// Kernel B: exclusive prefix sum over GC cells (single block, 1024 thr)
// ============================================================
__global__ __launch_bounds__(1024)
void scan_cells_kernel() {
    __shared__ int sh[1024];
    const int t = threadIdx.x;
    const int base = t * (GC / 1024);          // 4 cells per thread
    int loc[GC / 1024];
    int s = 0;
#pragma unroll
    for (int i = 0; i < GC / 1024; i++) { loc[i] = s; s += g_cellCnt[base + i]; }
    sh[t] = s;
    __syncthreads();
    for (int d = 1; d < 1024; d <<= 1) {       // Hillis-Steele inclusive scan
        int v = (t >= d) ? sh[t - d] : 0;
        __syncthreads();
        sh[t] += v;
        __syncthreads();
    }
    int off = sh[t] - s;                       // exclusive prefix of totals
#pragma unroll
    for (int i = 0; i < GC / 1024; i++) {
        int v = off + loc[i];
        g_cellStart[base + i] = v;
        g_cellPtr[base + i]   = v;
    }
    if (t == 1023) g_cellStart[GC] = off + s;
}

// ============================================================
// Kernel C: scatter points into cell-sorted order
// ============================================================
__global__ void scatter_kernel(int n) {
    int i = blockIdx.x * blockDim.x + threadIdx.x;
    if (i < n) {
        int dst = atomicAdd(&g_cellPtr[g_pcell[i]], 1);
        g_spos4[dst] = g_pos4[i];
        g_sid[dst]   = i;
    }
}

// ============================================================
// Kernel 1a: grid KNN — WARP per sorted query, APPEND-THEN-SELECT,
// with row-bounds prefetch (R16 proven).
// ============================================================
__global__ __launch_bounds__(256)
void knn_grid_kernel(int n) {
    __shared__ unsigned long long surv[8][SURVCAP];

    const int w    = threadIdx.x >> 5;
    const int lane = threadIdx.x & 31;
    const int s    = blockIdx.x * 8 + w;       // sorted query index

    const float4 qp = g_spos4[s];
    const float thr = fminf(knn_thr(qp.w, n), RCAP2);
    const float r   = sqrtf(thr);

    const int lx = cell1d(qp.x - r), hx = cell1d(qp.x + r);
    const int ly = cell1d(qp.y - r), hy = cell1d(qp.y + r);
    const int lz = cell1d(qp.z - r), hz = cell1d(qp.z + r);
    const int ny = hy - ly + 1;
    const int nrows = ny * (hz - lz + 1);      // <= 49 when cap-hit

    surv[w][lane]      = ~0ULL;
    surv[w][lane + 32] = ~0ULL;

    int cnt = 0;
    const unsigned below = (1u << lane) - 1u;

    for (int rb = 0; rb < nrows; rb += 32) {
        // parallel row-bounds prefetch: lane i -> row rb+i
        int ri = rb + lane;
        int s0 = 0, e0 = 0;
        if (ri < nrows) {
            int cz = lz + ri / ny;
            int cy = ly + ri - (ri / ny) * ny;
            int rowb = (cz * GRES + cy) * GRES;
            s0 = g_cellStart[rowb + lx];
            e0 = g_cellStart[rowb + hx + 1];
        }
        const int rcnt = min(32, nrows - rb);
        for (int rr = 0; rr < rcnt; rr++) {    // warp-uniform
            const int t0 = __shfl_sync(FULLMASK, s0, rr);
            const int t1 = __shfl_sync(FULLMASK, e0, rr);
            for (int tb = t0; tb < t1; tb += 32) {
                const int t  = tb + lane;
                const int tc = min(t, n - 1);
                float4 p = g_spos4[tc];                // coalesced LDG.128
                int   oj = g_sid[tc];
                float dot = fmaf(qp.x, p.x, fmaf(qp.y, p.y, qp.z * p.z));
                float d = fmaf(-2.0f, dot, qp.w + p.w);   // ref formula
                int valid = (t < t1) & (t != s) & (d < thr);
                unsigned long long key =
                    (((unsigned long long)__float_as_uint(fmaxf(d, 0.0f))) << 32)
                    | (unsigned)oj;
                unsigned m = __ballot_sync(FULLMASK, valid != 0);
                int idx = cnt + __popc(m & below);
                sts_pred(&surv[w][min(idx, SURVCAP - 1)], key,
                         valid & (idx < SURVCAP));
                cnt += __popc(m);
            }
        }
    }
    __syncwarp();

    const int orig = g_sid[s];
    const int bad = (cnt < KNN) | (cnt > SURVCAP);
    if (lane == 0) g_flag[orig] = bad;
    if (!bad) {                                // warp-uniform
        unsigned long long a = surv[w][lane];
        unsigned long long b = surv[w][lane + 32];
        unsigned long long keep = ~0ULL;
#pragma unroll
        for (int rr = 0; rr < KNN; rr++) {
            unsigned long long mn = umin64(a, b);
#pragma unroll
            for (int off = 16; off; off >>= 1)
                mn = umin64(mn, __shfl_xor_sync(FULLMASK, mn, off));
            if (lane == rr) keep = mn;         // SEL, no branch
            if (a == mn) a = ~0ULL;            // keys unique (idx unique)
            if (b == mn) b = ~0ULL;
        }
        if (lane < KNN)
            g_knn[orig * KNN + lane] = (int)(keep & 0xffffffffu);
    }
}

// ============================================================
// Kernel 1b: exact fallback — BLOCK per flagged query (R17).
// Old version: 1 warp scanned all 8192 pairs with serially-exposed
// L2 latency (~73us of single-warp critical path, the real KNN cost).
// Now: 8 warps each scan 1/8 of the pairs (critical path /8, warps
// hide each other's latency), each keeps an exact top-16 of its slice
// via warp_insert64, then 8x16 keys merge in smem with 16 rounds of
// key-min-reduce. Keys = (dist_bits<<32|idx) -> exact tie-break.
// Non-flagged blocks exit after one uniform load.
// ============================================================
__device__ __forceinline__ void warp_insert64(unsigned long long kn,
                                              unsigned long long& bk,
                                              unsigned long long& worst,
                                              int lane) {
    unsigned long long bp = __shfl_up_sync(FULLMASK, bk, 1);
    unsigned gm = __ballot_sync(FULLMASK, (lane < KNN) && (bk > kn));
    int pos = __ffs(gm) - 1;            // gm != 0 since bk[15] > kn
    if (lane < KNN) {
        if (lane > pos)       bk = bp;
        else if (lane == pos) bk = kn;
    }
    worst = __shfl_sync(FULLMASK, bk, KNN - 1);
}

__global__ __launch_bounds__(256)
void knn_fallback_kernel(int n) {
    const int q = blockIdx.x;
    if (g_flag[q] == 0) return;        // uniform early exit

    __shared__ unsigned long long lists[8 * KNN];

    const int w    = threadIdx.x >> 5;
    const int lane = threadIdx.x & 31;

    const float4 qp = g_pos4[q];
    const unsigned long long qx2 = pk2(qp.x, qp.x);
    const unsigned long long qy2 = pk2(qp.y, qp.y);
    const unsigned long long qz2 = pk2(qp.z, qp.z);
    const unsigned long long qw2 = pk2(qp.w, qp.w);
    const unsigned long long M2  = pk2(-2.0f, -2.0f);

    unsigned long long bk = ~0ULL;
    unsigned long long worst = ~0ULL;

    const int pairsPerWarp = (n / 2) / 8;      // 1024
    const int pbeg = w * pairsPerWarp;
    const int pend = pbeg + pairsPerWarp;

    for (int base = pbeg; base < pend; base += 32) {
        ulonglong2 A = g_pairA[base + lane];
        ulonglong2 B = g_pairB[base + lane];
        unsigned long long acc = mul2(qz2, B.x);
        acc = fma2(qy2, A.y, acc);
        acc = fma2(qx2, A.x, acc);
        unsigned long long dd = fma2(M2, acc, add2(qw2, B.y));
        float d0, d1;
        upk2(dd, d0, d1);
        int j0 = 2 * (base + lane);
        unsigned long long k0 =
            (((unsigned long long)__float_as_uint(fmaxf(d0, 0.0f))) << 32)
            | (unsigned)j0;
        unsigned long long k1 =
            (((unsigned long long)__float_as_uint(fmaxf(d1, 0.0f))) << 32)
            | (unsigned)(j0 + 1);
        bool v0 = (k0 < worst) && (j0 != q);
        bool v1 = (k1 < worst) && (j0 + 1 != q);

        unsigned m = __ballot_sync(FULLMASK, v0 | v1);
        while (m) {
            int src = __ffs(m) - 1;
            m &= m - 1;
            unsigned long long e0 = __shfl_sync(FULLMASK, k0, src);
            unsigned long long e1 = __shfl_sync(FULLMASK, k1, src);
            int jj = __shfl_sync(FULLMASK, j0, src);
            if (e0 < worst && jj != q)
                warp_insert64(e0, bk, worst, lane);
            if (e1 < worst && jj + 1 != q)
                warp_insert64(e1, bk, worst, lane);
        }
    }

    // publish per-warp top-16 (all real keys: slice size 2048 >> 16)
    if (lane < KNN)
        lists[w * KNN + lane] = bk;
    __syncthreads();

    // warp 0 merges 128 keys -> global top-16
    if (w == 0) {
        unsigned long long v0 = lists[lane];
        unsigned long long v1 = lists[lane + 32];
        unsigned long long v2 = lists[lane + 64];
        unsigned long long v3 = lists[lane + 96];
        unsigned long long keep = ~0ULL;
#pragma unroll
        for (int rr = 0; rr < KNN; rr++) {
            unsigned long long mn = umin64(umin64(v0, v1), umin64(v2, v3));
#pragma unroll
            for (int off = 16; off; off >>= 1)
                mn = umin64(mn, __shfl_xor_sync(FULLMASK, mn, off));
            if (lane == rr) keep = mn;
            if (v0 == mn) v0 = ~0ULL;          // keys unique (idx unique)
            if (v1 == mn) v1 = ~0ULL;
            if (v2 == mn) v2 = ~0ULL;
            if (v3 == mn) v3 = ~0ULL;
        }
        if (lane < KNN)
            g_knn[q * KNN + lane] = (int)(keep & 0xffffffffu);
    }
}

// ============================================================
// Kernel 2: B = x @ W1b ; C = x @ (W1a - W1b) + b1  (4-node blocked)
// ============================================================
__global__ __launch_bounds__(256)
void feat_kernel(const float* __restrict__ x,
                 const float* __restrict__ W1,
                 const float* __restrict__ b1, int n) {
    int t   = blockIdx.x * blockDim.x + threadIdx.x;
    int grp = t >> 6;
    int d   = t & 63;
    int n0  = grp * 4;
    if (n0 >= n) return;

    const float* x0 = x + n0 * CDIM;
    float a0 = 0, a1 = 0, a2 = 0, a3 = 0;
    float b0 = 0, b1v = 0, b2v = 0, b3 = 0;
#pragma unroll 8
    for (int c = 0; c < CDIM; c++) {
        float wa = W1[c * CDIM + d];
        float wb = W1[(CDIM + c) * CDIM + d];
        float x0v = x0[c];
        float x1v = x0[CDIM + c];
        float x2v = x0[2 * CDIM + c];
        float x3v = x0[3 * CDIM + c];
        a0 = fmaf(x0v, wa, a0);  b0  = fmaf(x0v, wb, b0);
        a1 = fmaf(x1v, wa, a1);  b1v = fmaf(x1v, wb, b1v);
        a2 = fmaf(x2v, wa, a2);  b2v = fmaf(x2v, wb, b2v);
        a3 = fmaf(x3v, wa, a3);  b3  = fmaf(x3v, wb, b3);
    }
    float bias = b1[d];
    g_B[(n0 + 0) * CDIM + d] = b0;   g_C[(n0 + 0) * CDIM + d] = a0 - b0  + bias;
    g_B[(n0 + 1) * CDIM + d] = b1v;  g_C[(n0 + 1) * CDIM + d] = a1 - b1v + bias;
    g_B[(n0 + 2) * CDIM + d] = b2v;  g_C[(n0 + 2) * CDIM + d] = a2 - b2v + bias;
    g_B[(n0 + 3) * CDIM + d] = b3;   g_C[(n0 + 3) * CDIM + d] = a3 - b3  + bias;
}

// ============================================================
// Kernel 3: edge — PROVEN R8/R13 monolithic e-outer kernel (88us).
// ============================================================
#define GSTRIDE 20
__global__ __launch_bounds__(64)
void edge_kernel(const float* __restrict__ W2,
                 const float* __restrict__ b2,
                 float* __restrict__ out, int n) {
    __shared__ __align__(16) float gsT[2][CDIM][GSTRIDE];
    const int d = threadIdx.x;
    const float b2d = b2[d];
    const int n0 = blockIdx.x * NODES_PER_BLOCK;

    float bv[KNN];
    float cv;
    {
        const int4* jr = (const int4*)&g_knn[n0 * KNN];
        int4 j4[4];
#pragma unroll
        for (int v = 0; v < 4; v++) j4[v] = jr[v];
        const int* jv = (const int*)j4;
        cv = g_C[n0 * CDIM + d];
#pragma unroll
        for (int k = 0; k < KNN; k++)
            bv[k] = g_B[jv[k] * CDIM + d];
    }

    for (int i = 0; i < NODES_PER_BLOCK; i++) {
        const int buf = i & 1;
        const int nn  = n0 + i;

#pragma unroll
        for (int k2 = 0; k2 < KNN / 2; k2++) {
            float2 gg;
            gg.x = fmaxf(cv + bv[2 * k2],     0.0f);
            gg.y = fmaxf(cv + bv[2 * k2 + 1], 0.0f);
            *(float2*)&gsT[buf][d][2 * k2] = gg;
        }

        if (i + 1 < NODES_PER_BLOCK) {
            const int nn1 = nn + 1;
            const int4* jr = (const int4*)&g_knn[nn1 * KNN];
            int4 j4[4];
#pragma unroll
            for (int v = 0; v < 4; v++) j4[v] = jr[v];
            const int* jv = (const int*)j4;
            cv = g_C[nn1 * CDIM + d];
#pragma unroll
            for (int k = 0; k < KNN; k++)
                bv[k] = g_B[jv[k] * CDIM + d];
        }
        __syncthreads();

        unsigned long long acc[8];
#pragma unroll
        for (int j = 0; j < 8; j++) acc[j] = 0ULL;
#pragma unroll 8
        for (int e = 0; e < CDIM; e++) {
            float wv = W2[e * CDIM + d];
            unsigned long long w2 = pk2(wv, wv);
            const ulonglong2* gp = (const ulonglong2*)&gsT[buf][e][0];
            ulonglong2 Ga = gp[0];
            ulonglong2 Gb = gp[1];
            acc[0] = fma2(Ga.x, w2, acc[0]);
            acc[1] = fma2(Ga.y, w2, acc[1]);
            acc[2] = fma2(Gb.x, w2, acc[2]);
            acc[3] = fma2(Gb.y, w2, acc[3]);
            const ulonglong2* gq = (const ulonglong2*)&gsT[buf][e][8];
            ulonglong2 Gc = gq[0];
            ulonglong2 Gd = gq[1];
            acc[4] = fma2(Gc.x, w2, acc[4]);
            acc[5] = fma2(Gd.x, w2, acc[5]);
            acc[6] = fma2(Gc.y, w2, acc[6]);
            acc[7] = fma2(Gd.y, w2, acc[7]);
        }
        float m = -3.4e38f;
#pragma unroll
        for (int j = 0; j < 8; j++) {
            float lo, hi;
            upk2(acc[j], lo, hi);
            m = fmaxf(m, fmaxf(lo, hi));
        }
        out[nn * CDIM + d] = m + b2d;
    }
}

// ============================================================
extern "C" void kernel_launch(void* const* d_in, const int* in_sizes, int n_in,
                              void* d_out, int out_size) {
    const float* x   = (const float*)d_in[0];
    const float* pos = (const float*)d_in[1];
    const float* W1  = (const float*)d_in[2];
    const float* b1  = (const float*)d_in[3];
    const float* W2  = (const float*)d_in[4];
    const float* b2  = (const float*)d_in[5];
    float* out = (float*)d_out;

    int n = in_sizes[1] / 3;
    if (n > NMAX) n = NMAX;

    zero_cells_kernel<<<GC / 256, 256>>>();
    pack_pos_kernel<<<(n / 2 + 255) / 256, 256>>>(pos, n);
    scan_cells_kernel<<<1, 1024>>>();
    scatter_kernel<<<(n + 255) / 256, 256>>>(n);
    knn_grid_kernel<<<(n + 7) / 8, 256>>>(n);
    knn_fallback_kernel<<<n, 256>>>(n);
    feat_kernel<<<(n * CDIM / 4 + 255) / 256, 256>>>(x, W1, b1, n);
    edge_kernel<<<n / NODES_PER_BLOCK, CDIM>>>(W2, b2, out, n);
}